// round 14
// baseline (speedup 1.0000x reference)
#include <cuda_runtime.h>
#include <cuda_bf16.h>
#include <cstdint>

// out = x @ Weff + bias;  Weff[8m+p, f] = sum_k scale[k,f]*sign(bit(7-p) of binary[k,m,f])
// prep: build bf16 hi/lo Weff^T and x-split into SW128-swizzled 8KB chunk-tiles;
//       seed out with bias.
// gemm: 144 CTAs (12 f x 4 m x 3 k-splits), K=256 as 4 chunks of 64,
//       cp.async.bulk (1 op / 8KB tile) + mbarrier 3-stage pipeline,
//       fused 3-segment HMMA, red.global.add epilogue.

#define NX 768
#define NF 768
#define NM 256
#define NG 96

#define SPLITS 3
#define KCTA 256
#define NCH 4             // chunks of 64 per CTA
#define NKC 12            // total k-chunks (NX/64)
#define TILEH 4096        // halves per 64x64 tile block (8192 bytes)

// chunk-tile blocks: g_a*[mt(4)][kc(12)] and g_b*[ft(12)][kc(12)], each 8KB SW128
__device__ __nv_bfloat16 g_ah[4 * NKC * TILEH];
__device__ __nv_bfloat16 g_al[4 * NKC * TILEH];
__device__ __nv_bfloat16 g_bh[12 * NKC * TILEH];
__device__ __nv_bfloat16 g_bl[12 * NKC * TILEH];

// ---------------------------------------------------------------------------
#define SWZ(o) ((o) ^ (((o) >> 3) & 0x70))   // Swizzle<3,4,3> on 128B rows

union B2U { __nv_bfloat162 h2; uint32_t u; };
__device__ __forceinline__ uint32_t pk2(__nv_bfloat16 a, __nv_bfloat16 b) {
    B2U t; t.h2 = __halves2bfloat162(a, b); return t.u;
}
__device__ __forceinline__ uint32_t smem_u32(const void* p) {
    uint32_t a;
    asm("{ .reg .u64 t; cvta.to.shared.u64 t, %1; cvt.u32.u64 %0, t; }"
        : "=r"(a) : "l"(p));
    return a;
}

#define LDSM4(r, addr) \
    asm volatile("ldmatrix.sync.aligned.m8n8.x4.shared.b16 {%0,%1,%2,%3}, [%4];" \
                 : "=r"((r)[0]), "=r"((r)[1]), "=r"((r)[2]), "=r"((r)[3]) : "r"(addr))

#define MMA16816(c, a, bb0, bb1) \
    asm volatile("mma.sync.aligned.m16n8k16.row.col.f32.bf16.bf16.f32 " \
                 "{%0,%1,%2,%3}, {%4,%5,%6,%7}, {%8,%9}, {%0,%1,%2,%3};" \
                 : "+f"((c)[0]), "+f"((c)[1]), "+f"((c)[2]), "+f"((c)[3]) \
                 : "r"((a)[0]), "r"((a)[1]), "r"((a)[2]), "r"((a)[3]), \
                   "r"(bb0), "r"(bb1))

#define MBAR_INIT(a, n) \
    asm volatile("mbarrier.init.shared.b64 [%0], %1;" :: "r"(a), "r"((uint32_t)(n)) : "memory")
#define MBAR_EXPECT_TX(a, tx) \
    asm volatile("mbarrier.arrive.expect_tx.shared.b64 _, [%0], %1;" \
                 :: "r"(a), "r"((uint32_t)(tx)) : "memory")

__device__ __forceinline__ void mbar_wait(uint32_t mbar, uint32_t parity) {
    uint32_t done;
    asm volatile("{\n\t.reg .pred p;\n\t"
                 "mbarrier.try_wait.parity.acquire.cta.shared::cta.b64 p, [%1], %2;\n\t"
                 "selp.b32 %0, 1, 0, p;\n\t}"
                 : "=r"(done) : "r"(mbar), "r"(parity) : "memory");
    if (!done) {
        asm volatile("{\n\t.reg .pred P1;\n\t"
                     "W%=:\n\t"
                     "mbarrier.try_wait.parity.acquire.cta.shared::cta.b64 P1, [%0], %1, 0x989680;\n\t"
                     "@P1 bra.uni D%=;\n\t"
                     "bra.uni W%=;\n\t"
                     "D%=:\n\t}"
                     :: "r"(mbar), "r"(parity) : "memory");
    }
}

__device__ __forceinline__ void bulk_ld(uint32_t dst, const void* src, uint32_t mbar) {
    asm volatile("cp.async.bulk.shared::cta.global.mbarrier::complete_tx::bytes "
                 "[%0], [%1], %2, [%3];"
                 :: "r"(dst), "l"(src), "r"((uint32_t)8192), "r"(mbar) : "memory");
}

// ---------------------------------------------------------------------------
// Kernel 1 (prep): [0,288) build Bh/Bl; [288,384) split x; [384,576) seed bias.
// ---------------------------------------------------------------------------
__global__ __launch_bounds__(256)
void prep_kernel(const float* __restrict__ scale,
                 const int*   __restrict__ binary,
                 const float* __restrict__ x,
                 const float* __restrict__ bias,
                 float*       __restrict__ out) {
    const int b = blockIdx.x, tid = threadIdx.x;

    if (b < 288) {                       // ---- build Weff -> bf16 hi/lo tiles ----
        const int t  = b * 256 + tid;    // < 73728 = NG*NF
        const int f  = t % NF;           // coalesced reads
        const int gm = t / NF;           // 0..95 weight-group

        int   c[8];
        float s[8];
#pragma unroll
        for (int k = 0; k < 8; k++) {
            c[k] = binary[(k * NG + gm) * NF + f];
            s[k] = scale[k * NF + f];
        }
        float w[8];
#pragma unroll
        for (int p = 0; p < 8; p++) w[p] = 0.0f;
#pragma unroll
        for (int k = 0; k < 8; k++)
#pragma unroll
            for (int p = 0; p < 8; p++)
                w[p] += ((c[k] >> (7 - p)) & 1) ? s[k] : -s[k];

        __nv_bfloat16 hi[8], lo[8];
#pragma unroll
        for (int p = 0; p < 8; p++) {
            hi[p] = __float2bfloat16(w[p]);
            lo[p] = __float2bfloat16(w[p] - __bfloat162float(hi[p]));
        }
        // dest: block (ft, kc), swizzled row fl, k-offset (gm&7)*8 halves
        const int ft = f >> 6, fl = f & 63;
        const int kc = gm >> 3;
        const uint32_t off = (uint32_t)((ft * NKC + kc) * 8192)
                           + SWZ((uint32_t)(fl * 128 + (gm & 7) * 16));
        *(uint4*)((char*)g_bh + off) =
            make_uint4(pk2(hi[0], hi[1]), pk2(hi[2], hi[3]),
                       pk2(hi[4], hi[5]), pk2(hi[6], hi[7]));
        *(uint4*)((char*)g_bl + off) =
            make_uint4(pk2(lo[0], lo[1]), pk2(lo[2], lo[3]),
                       pk2(lo[4], lo[5]), pk2(lo[6], lo[7]));
    } else if (b < 384) {                // ---- split x -> Ah/Al tiles ----
        const int i8 = (b - 288) * 256 + tid;   // item of 8 floats, < 24576
        const int m  = i8 / (NX / 8);
        const int k8 = (i8 % (NX / 8)) * 8;
        float4 v0 = *(const float4*)(x + (size_t)m * NX + k8);
        float4 v1 = *(const float4*)(x + (size_t)m * NX + k8 + 4);

        __nv_bfloat16 h[8], l[8];
        const float vf[8] = {v0.x, v0.y, v0.z, v0.w, v1.x, v1.y, v1.z, v1.w};
#pragma unroll
        for (int p = 0; p < 8; p++) {
            h[p] = __float2bfloat16(vf[p]);
            l[p] = __float2bfloat16(vf[p] - __bfloat162float(h[p]));
        }
        const int mt = m >> 6, rl = m & 63;
        const int kc = k8 >> 6, kk = k8 & 63;
        const uint32_t off = (uint32_t)((mt * NKC + kc) * 8192)
                           + SWZ((uint32_t)(rl * 128 + kk * 2));
        *(uint4*)((char*)g_ah + off) =
            make_uint4(pk2(h[0], h[1]), pk2(h[2], h[3]),
                       pk2(h[4], h[5]), pk2(h[6], h[7]));
        *(uint4*)((char*)g_al + off) =
            make_uint4(pk2(l[0], l[1]), pk2(l[2], l[3]),
                       pk2(l[4], l[5]), pk2(l[6], l[7]));
    } else {                             // ---- seed out with bias ----
        const int idx = (b - 384) * 256 + tid;  // < 49152 = NM*NF/4
        ((float4*)out)[idx] = ((const float4*)bias)[idx % (NF / 4)];
    }
}

// ---------------------------------------------------------------------------
// Kernel 2: bulk-copy pipelined fused-segment HMMA GEMM, atomic epilogue.
// Grid (12, 4, 3) = 144 CTAs x 256 thr (8 warps, warp tile 16x32).
// smem: 3 stages x 4 tiles x 8KB = 96KB + mbarriers.
// ---------------------------------------------------------------------------
#define NSTAGE 3
#define STAGEB 32768                     // bytes per stage (AH|AL|BH|BL)
#define SM_MBAR (NSTAGE * STAGEB)        // 3 mbarriers at 98304..
#define SMEM_BYTES (SM_MBAR + 64)

__global__ __launch_bounds__(256)
void gemm_mma_kernel(float* __restrict__ out) {
    extern __shared__ __align__(128) char smc[];
    const uint32_t smb = smem_u32(smc);

    const int tid  = threadIdx.x;
    const int wid  = tid >> 5;
    const int lane = tid & 31;

    const int ft = blockIdx.x;            // f-tile
    const int mt = blockIdx.y;            // m-tile
    const int kz = blockIdx.z;            // k-split (4 chunks each)
    const int kc0 = kz * NCH;

    if (tid == 0) {
#pragma unroll
        for (int s = 0; s < NSTAGE; s++) MBAR_INIT(smb + SM_MBAR + 8 * s, 1);
    }
    asm volatile("fence.proxy.async.shared::cta;" ::: "memory");
    __syncthreads();

    auto issue_chunk = [&](int c, int s) {   // chunk c -> stage s (tid 0 only)
        const uint32_t mbar = smb + SM_MBAR + 8 * s;
        MBAR_EXPECT_TX(mbar, STAGEB);
        const int kc = kc0 + c;
        const uint32_t dst = smb + (uint32_t)s * STAGEB;
        bulk_ld(dst,         (const char*)g_ah + (size_t)(mt * NKC + kc) * 8192, mbar);
        bulk_ld(dst +  8192, (const char*)g_al + (size_t)(mt * NKC + kc) * 8192, mbar);
        bulk_ld(dst + 16384, (const char*)g_bh + (size_t)(ft * NKC + kc) * 8192, mbar);
        bulk_ld(dst + 24576, (const char*)g_bl + (size_t)(ft * NKC + kc) * 8192, mbar);
    };

    if (tid == 0) {
        issue_chunk(0, 0);
        issue_chunk(1, 1);
        issue_chunk(2, 2);
    }

    const int wm = (wid >> 1) * 16;       // 4 warps along m
    const int wn = (wid & 1) * 32;        // 2 warps along n

    float acc[4][4];
#pragma unroll
    for (int j = 0; j < 4; j++)
#pragma unroll
        for (int v = 0; v < 4; v++) acc[j][v] = 0.0f;

    const int ra  = wm + (lane & 15);
    const int rb0 = wn + (lane & 15);
    const uint32_t chi = (uint32_t)((lane >> 4) << 4);   // 16B col select

#pragma unroll
    for (int c = 0; c < NCH; c++) {
        const int s = c % NSTAGE;
        const uint32_t ph = (uint32_t)((c / NSTAGE) & 1);
        mbar_wait(smb + SM_MBAR + 8 * s, ph);

        const uint32_t AHb = smb + (uint32_t)s * STAGEB;
        const uint32_t ALb = AHb + 8192;
        const uint32_t BHb = AHb + 16384;
        const uint32_t BLb = AHb + 24576;

#pragma unroll
        for (int ks = 0; ks < 4; ks++) {
            const uint32_t cb = (uint32_t)(ks * 32) + chi;
            uint32_t ah[4], al[4], bh0[4], bh1[4], bl0[4], bl1[4];
            LDSM4(ah,  AHb + SWZ((uint32_t)(ra * 128) + cb));
            LDSM4(al,  ALb + SWZ((uint32_t)(ra * 128) + cb));
            LDSM4(bh0, BHb + SWZ((uint32_t)(rb0 * 128) + cb));
            LDSM4(bh1, BHb + SWZ((uint32_t)((rb0 + 16) * 128) + cb));
            LDSM4(bl0, BLb + SWZ((uint32_t)(rb0 * 128) + cb));
            LDSM4(bl1, BLb + SWZ((uint32_t)((rb0 + 16) * 128) + cb));

            MMA16816(acc[0], ah, bh0[0], bh0[2]);
            MMA16816(acc[1], ah, bh0[1], bh0[3]);
            MMA16816(acc[2], ah, bh1[0], bh1[2]);
            MMA16816(acc[3], ah, bh1[1], bh1[3]);

            MMA16816(acc[0], al, bh0[0], bh0[2]);
            MMA16816(acc[1], al, bh0[1], bh0[3]);
            MMA16816(acc[2], al, bh1[0], bh1[2]);
            MMA16816(acc[3], al, bh1[1], bh1[3]);

            MMA16816(acc[0], ah, bl0[0], bl0[2]);
            MMA16816(acc[1], ah, bl0[1], bl0[3]);
            MMA16816(acc[2], ah, bl1[0], bl1[2]);
            MMA16816(acc[3], ah, bl1[1], bl1[3]);
        }
        __syncthreads();                  // all warps done reading stage s
        if (tid == 0 && c + NSTAGE < NCH) issue_chunk(c + NSTAGE, s);
    }

    // ---- epilogue: accumulate into bias-seeded out ----
    const int rbase = mt * 64 + wm + (lane >> 2);
    const int cbase = ft * 64 + wn + (lane & 3) * 2;
#pragma unroll
    for (int ni = 0; ni < 4; ni++) {
        int col = cbase + ni * 8;
        float* p0 = out + (size_t)rbase * NF + col;
        float* p1 = out + (size_t)(rbase + 8) * NF + col;
        asm volatile("red.global.add.v2.f32 [%0], {%1, %2};"
                     :: "l"(p0), "f"(acc[ni][0]), "f"(acc[ni][1]) : "memory");
        asm volatile("red.global.add.v2.f32 [%0], {%1, %2};"
                     :: "l"(p1), "f"(acc[ni][2]), "f"(acc[ni][3]) : "memory");
    }
}

// ---------------------------------------------------------------------------
extern "C" void kernel_launch(void* const* d_in, const int* in_sizes, int n_in,
                              void* d_out, int out_size) {
    const float* x      = (const float*)d_in[0];
    const float* scale  = (const float*)d_in[1];
    const int*   binary = (const int*)  d_in[2];
    const float* bias   = (const float*)d_in[3];
    float*       out    = (float*)d_out;

    cudaFuncSetAttribute(gemm_mma_kernel,
                         cudaFuncAttributeMaxDynamicSharedMemorySize, SMEM_BYTES);

    prep_kernel<<<576, 256>>>(scale, binary, x, bias, out);

    dim3 grid(NF / 64, NM / 64, SPLITS);   // 12 x 4 x 3 = 144 CTAs
    gemm_mma_kernel<<<grid, 256, SMEM_BYTES>>>(out);
}

// round 15
// speedup vs baseline: 1.0104x; 1.0104x over previous
#include <cuda_runtime.h>
#include <cuda_bf16.h>
#include <cstdint>

// out = x @ Weff + bias;  Weff[8m+p, f] = sum_k scale[k,f]*sign(bit(7-p) of binary[k,m,f])
// prep: build bf16 hi/lo Weff^T and x-split into SW128-swizzled 8KB chunk-tiles;
//       seed out with bias.
// gemm: 144 CTAs (12 f x 4 m x 3 k-splits), K=256 as 4 chunks of 64,
//       cp.async.bulk + mbarrier 3-stage pipeline, warp grid 2m x 2n x 2k
//       (warp tile 32x32x32), fused 3-segment HMMA, red.global.add epilogue.

#define NX 768
#define NF 768
#define NM 256
#define NG 96

#define SPLITS 3
#define NCH 4             // chunks of 64 per CTA
#define NKC 12            // total k-chunks (NX/64)
#define TILEH 4096        // halves per 64x64 tile block (8192 bytes)

__device__ __nv_bfloat16 g_ah[4 * NKC * TILEH];
__device__ __nv_bfloat16 g_al[4 * NKC * TILEH];
__device__ __nv_bfloat16 g_bh[12 * NKC * TILEH];
__device__ __nv_bfloat16 g_bl[12 * NKC * TILEH];

// ---------------------------------------------------------------------------
#define SWZ(o) ((o) ^ (((o) >> 3) & 0x70))   // Swizzle<3,4,3> on 128B rows

union B2U { __nv_bfloat162 h2; uint32_t u; };
__device__ __forceinline__ uint32_t pk2(__nv_bfloat16 a, __nv_bfloat16 b) {
    B2U t; t.h2 = __halves2bfloat162(a, b); return t.u;
}
__device__ __forceinline__ uint32_t smem_u32(const void* p) {
    uint32_t a;
    asm("{ .reg .u64 t; cvta.to.shared.u64 t, %1; cvt.u32.u64 %0, t; }"
        : "=r"(a) : "l"(p));
    return a;
}

#define LDSM4(r, addr) \
    asm volatile("ldmatrix.sync.aligned.m8n8.x4.shared.b16 {%0,%1,%2,%3}, [%4];" \
                 : "=r"((r)[0]), "=r"((r)[1]), "=r"((r)[2]), "=r"((r)[3]) : "r"(addr))

#define MMA16816(c, a, bb0, bb1) \
    asm volatile("mma.sync.aligned.m16n8k16.row.col.f32.bf16.bf16.f32 " \
                 "{%0,%1,%2,%3}, {%4,%5,%6,%7}, {%8,%9}, {%0,%1,%2,%3};" \
                 : "+f"((c)[0]), "+f"((c)[1]), "+f"((c)[2]), "+f"((c)[3]) \
                 : "r"((a)[0]), "r"((a)[1]), "r"((a)[2]), "r"((a)[3]), \
                   "r"(bb0), "r"(bb1))

#define MBAR_INIT(a, n) \
    asm volatile("mbarrier.init.shared.b64 [%0], %1;" :: "r"(a), "r"((uint32_t)(n)) : "memory")
#define MBAR_EXPECT_TX(a, tx) \
    asm volatile("mbarrier.arrive.expect_tx.shared.b64 _, [%0], %1;" \
                 :: "r"(a), "r"((uint32_t)(tx)) : "memory")

__device__ __forceinline__ void mbar_wait(uint32_t mbar, uint32_t parity) {
    uint32_t done;
    asm volatile("{\n\t.reg .pred p;\n\t"
                 "mbarrier.try_wait.parity.acquire.cta.shared::cta.b64 p, [%1], %2;\n\t"
                 "selp.b32 %0, 1, 0, p;\n\t}"
                 : "=r"(done) : "r"(mbar), "r"(parity) : "memory");
    if (!done) {
        asm volatile("{\n\t.reg .pred P1;\n\t"
                     "W%=:\n\t"
                     "mbarrier.try_wait.parity.acquire.cta.shared::cta.b64 P1, [%0], %1, 0x989680;\n\t"
                     "@P1 bra.uni D%=;\n\t"
                     "bra.uni W%=;\n\t"
                     "D%=:\n\t}"
                     :: "r"(mbar), "r"(parity) : "memory");
    }
}

__device__ __forceinline__ void bulk_ld(uint32_t dst, const void* src, uint32_t mbar) {
    asm volatile("cp.async.bulk.shared::cta.global.mbarrier::complete_tx::bytes "
                 "[%0], [%1], %2, [%3];"
                 :: "r"(dst), "l"(src), "r"((uint32_t)8192), "r"(mbar) : "memory");
}

// ---------------------------------------------------------------------------
// Kernel 1 (prep): [0,288) build Bh/Bl; [288,384) split x; [384,576) seed bias.
// (identical to round 14)
// ---------------------------------------------------------------------------
__global__ __launch_bounds__(256)
void prep_kernel(const float* __restrict__ scale,
                 const int*   __restrict__ binary,
                 const float* __restrict__ x,
                 const float* __restrict__ bias,
                 float*       __restrict__ out) {
    const int b = blockIdx.x, tid = threadIdx.x;

    if (b < 288) {
        const int t  = b * 256 + tid;    // < 73728 = NG*NF
        const int f  = t % NF;
        const int gm = t / NF;           // 0..95

        int   c[8];
        float s[8];
#pragma unroll
        for (int k = 0; k < 8; k++) {
            c[k] = binary[(k * NG + gm) * NF + f];
            s[k] = scale[k * NF + f];
        }
        float w[8];
#pragma unroll
        for (int p = 0; p < 8; p++) w[p] = 0.0f;
#pragma unroll
        for (int k = 0; k < 8; k++)
#pragma unroll
            for (int p = 0; p < 8; p++)
                w[p] += ((c[k] >> (7 - p)) & 1) ? s[k] : -s[k];

        __nv_bfloat16 hi[8], lo[8];
#pragma unroll
        for (int p = 0; p < 8; p++) {
            hi[p] = __float2bfloat16(w[p]);
            lo[p] = __float2bfloat16(w[p] - __bfloat162float(hi[p]));
        }
        const int ft = f >> 6, fl = f & 63;
        const int kc = gm >> 3;
        const uint32_t off = (uint32_t)((ft * NKC + kc) * 8192)
                           + SWZ((uint32_t)(fl * 128 + (gm & 7) * 16));
        *(uint4*)((char*)g_bh + off) =
            make_uint4(pk2(hi[0], hi[1]), pk2(hi[2], hi[3]),
                       pk2(hi[4], hi[5]), pk2(hi[6], hi[7]));
        *(uint4*)((char*)g_bl + off) =
            make_uint4(pk2(lo[0], lo[1]), pk2(lo[2], lo[3]),
                       pk2(lo[4], lo[5]), pk2(lo[6], lo[7]));
    } else if (b < 384) {
        const int i8 = (b - 288) * 256 + tid;   // < 24576
        const int m  = i8 / (NX / 8);
        const int k8 = (i8 % (NX / 8)) * 8;
        float4 v0 = *(const float4*)(x + (size_t)m * NX + k8);
        float4 v1 = *(const float4*)(x + (size_t)m * NX + k8 + 4);

        __nv_bfloat16 h[8], l[8];
        const float vf[8] = {v0.x, v0.y, v0.z, v0.w, v1.x, v1.y, v1.z, v1.w};
#pragma unroll
        for (int p = 0; p < 8; p++) {
            h[p] = __float2bfloat16(vf[p]);
            l[p] = __float2bfloat16(vf[p] - __bfloat162float(h[p]));
        }
        const int mt = m >> 6, rl = m & 63;
        const int kc = k8 >> 6, kk = k8 & 63;
        const uint32_t off = (uint32_t)((mt * NKC + kc) * 8192)
                           + SWZ((uint32_t)(rl * 128 + kk * 2));
        *(uint4*)((char*)g_ah + off) =
            make_uint4(pk2(h[0], h[1]), pk2(h[2], h[3]),
                       pk2(h[4], h[5]), pk2(h[6], h[7]));
        *(uint4*)((char*)g_al + off) =
            make_uint4(pk2(l[0], l[1]), pk2(l[2], l[3]),
                       pk2(l[4], l[5]), pk2(l[6], l[7]));
    } else {
        const int idx = (b - 384) * 256 + tid;  // < 49152
        ((float4*)out)[idx] = ((const float4*)bias)[idx % (NF / 4)];
    }
}

// ---------------------------------------------------------------------------
// Kernel 2: bulk-pipelined fused-segment HMMA GEMM, warp grid 2m x 2n x 2k.
// Grid (12, 4, 3) = 144 CTAs x 256 thr.
// ---------------------------------------------------------------------------
#define NSTAGE 3
#define STAGEB 32768
#define SM_MBAR (NSTAGE * STAGEB)
#define SMEM_BYTES (SM_MBAR + 64)

__global__ __launch_bounds__(256)
void gemm_mma_kernel(float* __restrict__ out) {
    extern __shared__ __align__(128) char smc[];
    const uint32_t smb = smem_u32(smc);

    const int tid  = threadIdx.x;
    const int wid  = tid >> 5;
    const int lane = tid & 31;

    const int ft = blockIdx.x;
    const int mt = blockIdx.y;
    const int kz = blockIdx.z;
    const int kc0 = kz * NCH;

    if (tid == 0) {
#pragma unroll
        for (int s = 0; s < NSTAGE; s++) MBAR_INIT(smb + SM_MBAR + 8 * s, 1);
    }
    asm volatile("fence.proxy.async.shared::cta;" ::: "memory");
    __syncthreads();

    auto issue_chunk = [&](int c, int s) {
        const uint32_t mbar = smb + SM_MBAR + 8 * s;
        MBAR_EXPECT_TX(mbar, STAGEB);
        const int kc = kc0 + c;
        const uint32_t dst = smb + (uint32_t)s * STAGEB;
        bulk_ld(dst,         (const char*)g_ah + (size_t)(mt * NKC + kc) * 8192, mbar);
        bulk_ld(dst +  8192, (const char*)g_al + (size_t)(mt * NKC + kc) * 8192, mbar);
        bulk_ld(dst + 16384, (const char*)g_bh + (size_t)(ft * NKC + kc) * 8192, mbar);
        bulk_ld(dst + 24576, (const char*)g_bl + (size_t)(ft * NKC + kc) * 8192, mbar);
    };

    if (tid == 0) {
        issue_chunk(0, 0);
        issue_chunk(1, 1);
        issue_chunk(2, 2);
    }

    // warp grid: wid = (wm2, wn2, wk2) -> 2 x 2 x 2; warp tile 32m x 32n x 32k
    const int wm = (wid & 1) * 32;        // m offset
    const int wn = ((wid >> 1) & 1) * 32; // n offset
    const int wk = (wid >> 2) * 32;       // k offset within chunk

    float acc[2][4][4];                   // [m-frag][n-octet][quad]
#pragma unroll
    for (int i = 0; i < 2; i++)
#pragma unroll
        for (int j = 0; j < 4; j++)
#pragma unroll
            for (int v = 0; v < 4; v++) acc[i][j][v] = 0.0f;

    const int ra  = wm + (lane & 15);     // A rows (ra, ra+16)
    const int rb  = wn + (lane & 15);     // B rows (rb, rb+16)
    const uint32_t chi = (uint32_t)((lane >> 4) << 4);   // 16B col select

#pragma unroll
    for (int c = 0; c < NCH; c++) {
        const int s = c % NSTAGE;
        const uint32_t ph = (uint32_t)((c / NSTAGE) & 1);
        mbar_wait(smb + SM_MBAR + 8 * s, ph);

        const uint32_t AHb = smb + (uint32_t)s * STAGEB;
        const uint32_t ALb = AHb + 8192;
        const uint32_t BHb = AHb + 16384;
        const uint32_t BLb = AHb + 24576;

#pragma unroll
        for (int ks = 0; ks < 2; ks++) {  // this warp's 2 ksteps (k16 each)
            const uint32_t cb = (uint32_t)(wk * 2 + ks * 32) + chi;  // byte col
            uint32_t ah0[4], ah1[4], al0[4], al1[4];
            uint32_t bh0[4], bh1[4], bl0[4], bl1[4];
            LDSM4(ah0, AHb + SWZ((uint32_t)(ra * 128) + cb));
            LDSM4(ah1, AHb + SWZ((uint32_t)((ra + 16) * 128) + cb));
            LDSM4(al0, ALb + SWZ((uint32_t)(ra * 128) + cb));
            LDSM4(al1, ALb + SWZ((uint32_t)((ra + 16) * 128) + cb));
            LDSM4(bh0, BHb + SWZ((uint32_t)(rb * 128) + cb));
            LDSM4(bh1, BHb + SWZ((uint32_t)((rb + 16) * 128) + cb));
            LDSM4(bl0, BLb + SWZ((uint32_t)(rb * 128) + cb));
            LDSM4(bl1, BLb + SWZ((uint32_t)((rb + 16) * 128) + cb));

            // Ah*Bh
            MMA16816(acc[0][0], ah0, bh0[0], bh0[2]);
            MMA16816(acc[0][1], ah0, bh0[1], bh0[3]);
            MMA16816(acc[0][2], ah0, bh1[0], bh1[2]);
            MMA16816(acc[0][3], ah0, bh1[1], bh1[3]);
            MMA16816(acc[1][0], ah1, bh0[0], bh0[2]);
            MMA16816(acc[1][1], ah1, bh0[1], bh0[3]);
            MMA16816(acc[1][2], ah1, bh1[0], bh1[2]);
            MMA16816(acc[1][3], ah1, bh1[1], bh1[3]);
            // Al*Bh
            MMA16816(acc[0][0], al0, bh0[0], bh0[2]);
            MMA16816(acc[0][1], al0, bh0[1], bh0[3]);
            MMA16816(acc[0][2], al0, bh1[0], bh1[2]);
            MMA16816(acc[0][3], al0, bh1[1], bh1[3]);
            MMA16816(acc[1][0], al1, bh0[0], bh0[2]);
            MMA16816(acc[1][1], al1, bh0[1], bh0[3]);
            MMA16816(acc[1][2], al1, bh1[0], bh1[2]);
            MMA16816(acc[1][3], al1, bh1[1], bh1[3]);
            // Ah*Bl
            MMA16816(acc[0][0], ah0, bl0[0], bl0[2]);
            MMA16816(acc[0][1], ah0, bl0[1], bl0[3]);
            MMA16816(acc[0][2], ah0, bl1[0], bl1[2]);
            MMA16816(acc[0][3], ah0, bl1[1], bl1[3]);
            MMA16816(acc[1][0], ah1, bl0[0], bl0[2]);
            MMA16816(acc[1][1], ah1, bl0[1], bl0[3]);
            MMA16816(acc[1][2], ah1, bl1[0], bl1[2]);
            MMA16816(acc[1][3], ah1, bl1[1], bl1[3]);
        }
        __syncthreads();
        if (tid == 0 && c + NSTAGE < NCH) issue_chunk(c + NSTAGE, s);
    }

    // ---- epilogue: accumulate into bias-seeded out ----
    const int rbase = mt * 64 + wm + (lane >> 2);
    const int cbase = ft * 64 + wn + (lane & 3) * 2;
#pragma unroll
    for (int mi = 0; mi < 2; mi++) {
#pragma unroll
        for (int ni = 0; ni < 4; ni++) {
            int row = rbase + mi * 16;
            int col = cbase + ni * 8;
            float* p0 = out + (size_t)row * NF + col;
            float* p1 = out + (size_t)(row + 8) * NF + col;
            asm volatile("red.global.add.v2.f32 [%0], {%1, %2};"
                         :: "l"(p0), "f"(acc[mi][ni][0]), "f"(acc[mi][ni][1]) : "memory");
            asm volatile("red.global.add.v2.f32 [%0], {%1, %2};"
                         :: "l"(p1), "f"(acc[mi][ni][2]), "f"(acc[mi][ni][3]) : "memory");
        }
    }
}

// ---------------------------------------------------------------------------
extern "C" void kernel_launch(void* const* d_in, const int* in_sizes, int n_in,
                              void* d_out, int out_size) {
    const float* x      = (const float*)d_in[0];
    const float* scale  = (const float*)d_in[1];
    const int*   binary = (const int*)  d_in[2];
    const float* bias   = (const float*)d_in[3];
    float*       out    = (float*)d_out;

    cudaFuncSetAttribute(gemm_mma_kernel,
                         cudaFuncAttributeMaxDynamicSharedMemorySize, SMEM_BYTES);

    prep_kernel<<<576, 256>>>(scale, binary, x, bias, out);

    dim3 grid(NF / 64, NM / 64, SPLITS);   // 12 x 4 x 3 = 144 CTAs
    gemm_mma_kernel<<<grid, 256, SMEM_BYTES>>>(out);
}